// round 13
// baseline (speedup 1.0000x reference)
#include <cuda_runtime.h>

// LSTM (H=64, in=1, T=1024, B=4096) + Linear(64->30), fp32.
// R12 (3079us) base + PACKED gate glue: the shfl pair-combine results stay
// as f32x2 -- (p+o), +x*wih, +bias done with add/fma.rn.f32x2 (6 packed ops
// per batch instead of 12 scalar), xv broadcast-packed once per batch.
// Activations on HW MUFU.TANH: tanh = tanh.approx.f32; sigmoid =
// 0.5*tanh(0.5x)+0.5. Skeleton: 147 blocks x 256 thr; khalf/j/bhalf
// decomposition; 4 gate rows x 32 k in registers; shfl.bfly(1) k-combine;
// divergence-free update of 7 owned batches; ping-pong h/x; 1 barrier/step.

#define HID      64
#define SEQ_T    1024
#define NBATCH   4096
#define NFC      30
#define NB       28
#define NTHREADS 256
#define XCHUNK   32
#define BPT      14       // batches touched per thread in matvec
#define BOWN     7        // batches owned per thread for c/h update

__device__ __forceinline__ float tanh_hw(float x) {
    float r; asm("tanh.approx.f32 %0, %1;" : "=f"(r) : "f"(x)); return r;
}
__device__ __forceinline__ float sigm(float x) {
    return fmaf(0.5f, tanh_hw(0.5f * x), 0.5f);
}
__device__ __forceinline__ float tanh_fast(float x) {
    return tanh_hw(x);
}

__device__ __forceinline__ unsigned long long pack2(float lo, float hi) {
    unsigned long long r;
    asm("mov.b64 %0, {%1, %2};" : "=l"(r) : "f"(lo), "f"(hi));
    return r;
}
__device__ __forceinline__ void unpack2(unsigned long long v, float& lo, float& hi) {
    asm("mov.b64 {%0, %1}, %2;" : "=f"(lo), "=f"(hi) : "l"(v));
}
__device__ __forceinline__ void ffma2(unsigned long long& d,
                                      unsigned long long a,
                                      unsigned long long b) {
    asm("fma.rn.f32x2 %0, %1, %2, %0;" : "+l"(d) : "l"(a), "l"(b));
}
__device__ __forceinline__ void fadd2(unsigned long long& d,
                                      unsigned long long a) {
    asm("add.rn.f32x2 %0, %0, %1;" : "+l"(d) : "l"(a));
}

__global__ void __launch_bounds__(NTHREADS, 1)
lstm_fused(const float* __restrict__ x,      // [B, T]
           const float* __restrict__ W_ih,   // [256]
           const float* __restrict__ W_hh,   // [256, 64]
           const float* __restrict__ b_ih,   // [256]
           const float* __restrict__ b_hh,   // [256]
           const float* __restrict__ fc_W,   // [30, 64]
           const float* __restrict__ fc_b,   // [30]
           float* __restrict__ out)          // [B, 30]
{
    __shared__ __align__(16) float h_sm[2][NB][HID];     // ping-pong hidden
    __shared__ __align__(16) float x_sm[2][NB][XCHUNK];  // ping-pong x chunks
    __shared__ __align__(16) float fcW_sm[NFC][HID];
    __shared__ float fcb_sm[NFC];

    const int tid   = threadIdx.x;
    const int khalf = tid & 1;          // k half: 0 -> k[0..31], 1 -> k[32..63]
    const int j     = (tid >> 1) & 63;  // hidden unit
    const int bhalf = tid >> 7;         // batch half (0/1)
    const int b0    = blockIdx.x * NB;

    // --- weights: 4 gate rows, my 32 k-values, rotated chunk order so the
    //     two khalves hit disjoint smem bank quads ---
    const int rI = j, rF = HID + j, rG = 2 * HID + j, rO = 3 * HID + j;
    unsigned long long wI[16], wF[16], wG[16], wO[16];
    int hoff[8];  // byte offsets into an h row for chunk i
#pragma unroll
    for (int i = 0; i < 8; ++i) {
        int kb = khalf * 32 + (((i + khalf) & 7) << 2);
        hoff[i] = kb * 4;
        wI[2*i]   = pack2(W_hh[rI*HID + kb],     W_hh[rI*HID + kb + 1]);
        wI[2*i+1] = pack2(W_hh[rI*HID + kb + 2], W_hh[rI*HID + kb + 3]);
        wF[2*i]   = pack2(W_hh[rF*HID + kb],     W_hh[rF*HID + kb + 1]);
        wF[2*i+1] = pack2(W_hh[rF*HID + kb + 2], W_hh[rF*HID + kb + 3]);
        wG[2*i]   = pack2(W_hh[rG*HID + kb],     W_hh[rG*HID + kb + 1]);
        wG[2*i+1] = pack2(W_hh[rG*HID + kb + 2], W_hh[rG*HID + kb + 3]);
        wO[2*i]   = pack2(W_hh[rO*HID + kb],     W_hh[rO*HID + kb + 1]);
        wO[2*i+1] = pack2(W_hh[rO*HID + kb + 2], W_hh[rO*HID + kb + 3]);
    }
    // packed (I,F)/(G,O) input-weight and bias constants
    const unsigned long long wih01  = pack2(W_ih[rI], W_ih[rF]);
    const unsigned long long wih23  = pack2(W_ih[rG], W_ih[rO]);
    const unsigned long long bias01 = pack2(b_ih[rI] + b_hh[rI], b_ih[rF] + b_hh[rF]);
    const unsigned long long bias23 = pack2(b_ih[rG] + b_hh[rG], b_ih[rO] + b_hh[rO]);

    // --- FC weights to smem; h buf0 zero; x buf0 prologue (t=0..31) ---
    for (int i = tid; i < NFC * HID; i += NTHREADS)
        (&fcW_sm[0][0])[i] = fc_W[i];
    for (int i = tid; i < NFC; i += NTHREADS)
        fcb_sm[i] = fc_b[i];
    for (int i = tid; i < NB * HID; i += NTHREADS)
        (&h_sm[0][0][0])[i] = 0.0f;
    for (int i = tid; i < NB * XCHUNK; i += NTHREADS) {
        int b  = i / XCHUNK;
        int tt = i % XCHUNK;
        int gb = b0 + b; if (gb >= NBATCH) gb = NBATCH - 1;
        (&x_sm[0][0][0])[i] = x[gb * SEQ_T + tt];
    }

    float c_reg[BOWN];
#pragma unroll
    for (int s = 0; s < BOWN; ++s) c_reg[s] = 0.0f;

    for (int t = 0; t < SEQ_T; ++t) {
        const int rb = t & 1;           // h read buffer
        const int wb = rb ^ 1;          // h write buffer
        const int xb = (t >> 5) & 1;    // x read buffer

        // prefetch NEXT x chunk into the other buffer
        if ((t & (XCHUNK - 1)) == 0 && t + XCHUNK < SEQ_T) {
            for (int i = tid; i < NB * XCHUNK; i += NTHREADS) {
                int b  = i / XCHUNK;
                int tt = i % XCHUNK;
                int gb = b0 + b; if (gb >= NBATCH) gb = NBATCH - 1;
                x_sm[xb ^ 1][b][tt] = x[gb * SEQ_T + t + XCHUNK + tt];
            }
        }
        __syncthreads();  // h[rb] from prev step + x visible

        const int tx = t & (XCHUNK - 1);
        float gq[BOWN][4];  // full gates for the 7 batches this thread owns

#pragma unroll
        for (int s = 0; s < BPT; ++s) {
            const int b = bhalf * BPT + s;
            const char* hbase = (const char*)&h_sm[rb][b][0];

            unsigned long long aI = 0ull, aF = 0ull, aG = 0ull, aO = 0ull;
#pragma unroll
            for (int i = 0; i < 8; ++i) {
                ulonglong2 hv = *(const ulonglong2*)(hbase + hoff[i]);
                ffma2(aI, wI[2*i], hv.x); ffma2(aI, wI[2*i+1], hv.y);
                ffma2(aF, wF[2*i], hv.x); ffma2(aF, wF[2*i+1], hv.y);
                ffma2(aG, wG[2*i], hv.x); ffma2(aG, wG[2*i+1], hv.y);
                ffma2(aO, wO[2*i], hv.x); ffma2(aO, wO[2*i+1], hv.y);
            }
            float lo, hi, pI, pF, pG, pO;
            unpack2(aI, lo, hi); pI = lo + hi;
            unpack2(aF, lo, hi); pF = lo + hi;
            unpack2(aG, lo, hi); pG = lo + hi;
            unpack2(aO, lo, hi); pO = lo + hi;

            // combine k-halves with the paired lane (lane ^ 1, same warp)
            unsigned long long p01 = pack2(pI, pF);
            unsigned long long p23 = pack2(pG, pO);
            unsigned long long o01 = __shfl_xor_sync(0xffffffffu, p01, 1);
            unsigned long long o23 = __shfl_xor_sync(0xffffffffu, p23, 1);

            // PACKED glue: g = (p + o) + xv*wih + bias, all f32x2
            const float xv = x_sm[xb][b][tx];
            const unsigned long long xv2 = pack2(xv, xv);
            fadd2(p01, o01);            // p01 = p + o   (I,F)
            ffma2(p01, xv2, wih01);     //      + xv*wih
            fadd2(p01, bias01);         //      + bias
            fadd2(p23, o23);            // same for (G,O)
            ffma2(p23, xv2, wih23);
            fadd2(p23, bias23);

            float gI, gF, gG, gO;
            unpack2(p01, gI, gF);
            unpack2(p23, gG, gO);

            // keep only batches this lane owns: khalf0 -> s 0..6, khalf1 -> 7..13
            if (s < BOWN) {
                if (khalf == 0) { gq[s][0]=gI; gq[s][1]=gF; gq[s][2]=gG; gq[s][3]=gO; }
            } else {
                if (khalf == 1) { gq[s-BOWN][0]=gI; gq[s-BOWN][1]=gF; gq[s-BOWN][2]=gG; gq[s-BOWN][3]=gO; }
            }
        }

        // ---- divergence-free update: each lane updates its 7 owned batches ----
#pragma unroll
        for (int q = 0; q < BOWN; ++q) {
            const int b = bhalf * BPT + khalf * BOWN + q;
            float ci = fmaf(sigm(gq[q][1]), c_reg[q],
                            sigm(gq[q][0]) * tanh_fast(gq[q][2]));
            c_reg[q] = ci;
            h_sm[wb][b][j] = sigm(gq[q][3]) * tanh_fast(ci);
        }
    }

    __syncthreads();  // final h (buffer 0, SEQ_T even) ready

    // ---- FC: out[b, f] = h[b,:] . fc_W[f,:] + fc_b[f] ----
    for (int task = tid; task < NB * NFC; task += NTHREADS) {
        int b = task / NFC;
        int f = task % NFC;
        int gb = b0 + b;
        if (gb < NBATCH) {
            float s = fcb_sm[f];
#pragma unroll
            for (int k = 0; k < HID; ++k)
                s = fmaf(h_sm[0][b][k], fcW_sm[f][k], s);
            out[gb * NFC + f] = s;
        }
    }
}

extern "C" void kernel_launch(void* const* d_in, const int* in_sizes, int n_in,
                              void* d_out, int out_size) {
    const float* x    = (const float*)d_in[0];
    const float* W_ih = (const float*)d_in[1];
    const float* W_hh = (const float*)d_in[2];
    const float* b_ih = (const float*)d_in[3];
    const float* b_hh = (const float*)d_in[4];
    const float* fc_W = (const float*)d_in[5];
    const float* fc_b = (const float*)d_in[6];
    (void)in_sizes; (void)n_in; (void)out_size;

    const int grid = (NBATCH + NB - 1) / NB;  // 147 blocks, 1 per SM
    lstm_fused<<<grid, NTHREADS>>>(x, W_ih, W_hh, b_ih, b_hh, fc_W, fc_b,
                                   (float*)d_out);
}

// round 14
// speedup vs baseline: 1.0771x; 1.0771x over previous
#include <cuda_runtime.h>

// LSTM (H=64, in=1, T=1024, B=4096) + Linear(64->30), fp32.
// R12 (3079us) inner loop, repackaged as TWO INDEPENDENT 128-THREAD BLOCKS
// PER SM: NB=14/block, grid=294, __launch_bounds__(128,2). Each SMSP hosts
// one warp of block A and one of block B with independent barriers -> while
// one block runs its MUFU-bound update / waits at its barrier, the other
// issues FFMA2. Per-thread work/layout identical to R12 (4 gate rows x 32 k
// in registers, shfl.bfly(1) k-combine, scalar glue, HW tanh). i/f/o rows
// pre-scaled by 0.5 so sigmoid needs no input scaling (exact, bitwise-same).

#define HID      64
#define SEQ_T    1024
#define NBATCH   4096
#define NFC      30
#define NB       14       // batches per block
#define NTHREADS 128
#define XCHUNK   32
#define BPT      14       // batches touched per thread in matvec
#define BOWN     7        // batches owned per thread for c/h update

__device__ __forceinline__ float tanh_hw(float x) {
    float r; asm("tanh.approx.f32 %0, %1;" : "=f"(r) : "f"(x)); return r;
}
// input already halved (weights pre-scaled by 0.5)
__device__ __forceinline__ float sigm_h(float xh) {
    return fmaf(0.5f, tanh_hw(xh), 0.5f);
}

__device__ __forceinline__ unsigned long long pack2(float lo, float hi) {
    unsigned long long r;
    asm("mov.b64 %0, {%1, %2};" : "=l"(r) : "f"(lo), "f"(hi));
    return r;
}
__device__ __forceinline__ void unpack2(unsigned long long v, float& lo, float& hi) {
    asm("mov.b64 {%0, %1}, %2;" : "=f"(lo), "=f"(hi) : "l"(v));
}
__device__ __forceinline__ void ffma2(unsigned long long& d,
                                      unsigned long long a,
                                      unsigned long long b) {
    asm("fma.rn.f32x2 %0, %1, %2, %0;" : "+l"(d) : "l"(a), "l"(b));
}

__global__ void __launch_bounds__(NTHREADS, 2)
lstm_fused(const float* __restrict__ x,      // [B, T]
           const float* __restrict__ W_ih,   // [256]
           const float* __restrict__ W_hh,   // [256, 64]
           const float* __restrict__ b_ih,   // [256]
           const float* __restrict__ b_hh,   // [256]
           const float* __restrict__ fc_W,   // [30, 64]
           const float* __restrict__ fc_b,   // [30]
           float* __restrict__ out)          // [B, 30]
{
    __shared__ __align__(16) float h_sm[2][NB][HID];     // ping-pong hidden
    __shared__ __align__(16) float x_sm[2][NB][XCHUNK];  // ping-pong x chunks
    __shared__ __align__(16) float fcW_sm[NFC][HID];
    __shared__ float fcb_sm[NFC];

    const int tid   = threadIdx.x;
    const int khalf = tid & 1;          // k half: 0 -> k[0..31], 1 -> k[32..63]
    const int j     = tid >> 1;         // hidden unit 0..63
    const int b0    = blockIdx.x * NB;

    // --- weights: 4 gate rows, my 32 k-values, rotated chunk order so the
    //     two khalves hit disjoint smem bank quads. i/f/o rows scaled 0.5 ---
    const int rI = j, rF = HID + j, rG = 2 * HID + j, rO = 3 * HID + j;
    unsigned long long wI[16], wF[16], wG[16], wO[16];
    int hoff[8];  // byte offsets into an h row for chunk i
#pragma unroll
    for (int i = 0; i < 8; ++i) {
        int kb = khalf * 32 + (((i + khalf) & 7) << 2);
        hoff[i] = kb * 4;
        wI[2*i]   = pack2(0.5f*W_hh[rI*HID + kb],     0.5f*W_hh[rI*HID + kb + 1]);
        wI[2*i+1] = pack2(0.5f*W_hh[rI*HID + kb + 2], 0.5f*W_hh[rI*HID + kb + 3]);
        wF[2*i]   = pack2(0.5f*W_hh[rF*HID + kb],     0.5f*W_hh[rF*HID + kb + 1]);
        wF[2*i+1] = pack2(0.5f*W_hh[rF*HID + kb + 2], 0.5f*W_hh[rF*HID + kb + 3]);
        wG[2*i]   = pack2(W_hh[rG*HID + kb],          W_hh[rG*HID + kb + 1]);
        wG[2*i+1] = pack2(W_hh[rG*HID + kb + 2],      W_hh[rG*HID + kb + 3]);
        wO[2*i]   = pack2(0.5f*W_hh[rO*HID + kb],     0.5f*W_hh[rO*HID + kb + 1]);
        wO[2*i+1] = pack2(0.5f*W_hh[rO*HID + kb + 2], 0.5f*W_hh[rO*HID + kb + 3]);
    }
    const float wihI = 0.5f * W_ih[rI], wihF = 0.5f * W_ih[rF];
    const float wihG = W_ih[rG],        wihO = 0.5f * W_ih[rO];
    const float bI = 0.5f * (b_ih[rI] + b_hh[rI]);
    const float bF = 0.5f * (b_ih[rF] + b_hh[rF]);
    const float bG = b_ih[rG] + b_hh[rG];
    const float bO = 0.5f * (b_ih[rO] + b_hh[rO]);

    // --- FC weights to smem; h buf0 zero; x buf0 prologue (t=0..31) ---
    for (int i = tid; i < NFC * HID; i += NTHREADS)
        (&fcW_sm[0][0])[i] = fc_W[i];
    for (int i = tid; i < NFC; i += NTHREADS)
        fcb_sm[i] = fc_b[i];
    for (int i = tid; i < NB * HID; i += NTHREADS)
        (&h_sm[0][0][0])[i] = 0.0f;
    for (int i = tid; i < NB * XCHUNK; i += NTHREADS) {
        int b  = i / XCHUNK;
        int tt = i % XCHUNK;
        int gb = b0 + b; if (gb >= NBATCH) gb = NBATCH - 1;
        (&x_sm[0][0][0])[i] = x[gb * SEQ_T + tt];
    }

    float c_reg[BOWN];
#pragma unroll
    for (int s = 0; s < BOWN; ++s) c_reg[s] = 0.0f;

    for (int t = 0; t < SEQ_T; ++t) {
        const int rb = t & 1;           // h read buffer
        const int wb = rb ^ 1;          // h write buffer
        const int xb = (t >> 5) & 1;    // x read buffer

        // prefetch NEXT x chunk into the other buffer
        if ((t & (XCHUNK - 1)) == 0 && t + XCHUNK < SEQ_T) {
            for (int i = tid; i < NB * XCHUNK; i += NTHREADS) {
                int b  = i / XCHUNK;
                int tt = i % XCHUNK;
                int gb = b0 + b; if (gb >= NBATCH) gb = NBATCH - 1;
                x_sm[xb ^ 1][b][tt] = x[gb * SEQ_T + t + XCHUNK + tt];
            }
        }
        __syncthreads();  // h[rb] from prev step + x visible (block-local)

        const int tx = t & (XCHUNK - 1);
        float gq[BOWN][4];  // gates (I',F',G,O') of the 7 owned batches

#pragma unroll
        for (int s = 0; s < BPT; ++s) {
            const int b = s;
            const char* hbase = (const char*)&h_sm[rb][b][0];

            unsigned long long aI = 0ull, aF = 0ull, aG = 0ull, aO = 0ull;
#pragma unroll
            for (int i = 0; i < 8; ++i) {
                ulonglong2 hv = *(const ulonglong2*)(hbase + hoff[i]);
                ffma2(aI, wI[2*i], hv.x); ffma2(aI, wI[2*i+1], hv.y);
                ffma2(aF, wF[2*i], hv.x); ffma2(aF, wF[2*i+1], hv.y);
                ffma2(aG, wG[2*i], hv.x); ffma2(aG, wG[2*i+1], hv.y);
                ffma2(aO, wO[2*i], hv.x); ffma2(aO, wO[2*i+1], hv.y);
            }
            float lo, hi, pI, pF, pG, pO;
            unpack2(aI, lo, hi); pI = lo + hi;
            unpack2(aF, lo, hi); pF = lo + hi;
            unpack2(aG, lo, hi); pG = lo + hi;
            unpack2(aO, lo, hi); pO = lo + hi;

            // combine k-halves with the paired lane (lane ^ 1, same warp)
            unsigned long long p01 = pack2(pI, pF);
            unsigned long long p23 = pack2(pG, pO);
            unsigned long long o01 = __shfl_xor_sync(0xffffffffu, p01, 1);
            unsigned long long o23 = __shfl_xor_sync(0xffffffffu, p23, 1);
            float oI, oF, oG, oO;
            unpack2(o01, oI, oF);
            unpack2(o23, oG, oO);

            const float xv = x_sm[xb][b][tx];
            float gI = pI + oI + fmaf(xv, wihI, bI);
            float gF = pF + oF + fmaf(xv, wihF, bF);
            float gG = pG + oG + fmaf(xv, wihG, bG);
            float gO = pO + oO + fmaf(xv, wihO, bO);

            // keep only batches this lane owns: khalf0 -> s 0..6, khalf1 -> 7..13
            if (s < BOWN) {
                if (khalf == 0) { gq[s][0]=gI; gq[s][1]=gF; gq[s][2]=gG; gq[s][3]=gO; }
            } else {
                if (khalf == 1) { gq[s-BOWN][0]=gI; gq[s-BOWN][1]=gF; gq[s-BOWN][2]=gG; gq[s-BOWN][3]=gO; }
            }
        }

        // ---- divergence-free update: each lane updates its 7 owned batches ----
#pragma unroll
        for (int q = 0; q < BOWN; ++q) {
            const int b = khalf * BOWN + q;
            float ci = fmaf(sigm_h(gq[q][1]), c_reg[q],
                            sigm_h(gq[q][0]) * tanh_hw(gq[q][2]));
            c_reg[q] = ci;
            h_sm[wb][b][j] = sigm_h(gq[q][3]) * tanh_hw(ci);
        }
    }

    __syncthreads();  // final h (buffer 0, SEQ_T even) ready

    // ---- FC: out[b, f] = h[b,:] . fc_W[f,:] + fc_b[f] ----
    for (int task = tid; task < NB * NFC; task += NTHREADS) {
        int b = task / NFC;
        int f = task % NFC;
        int gb = b0 + b;
        if (gb < NBATCH) {
            float s = fcb_sm[f];
#pragma unroll
            for (int k = 0; k < HID; ++k)
                s = fmaf(h_sm[0][b][k], fcW_sm[f][k], s);
            out[gb * NFC + f] = s;
        }
    }
}

extern "C" void kernel_launch(void* const* d_in, const int* in_sizes, int n_in,
                              void* d_out, int out_size) {
    const float* x    = (const float*)d_in[0];
    const float* W_ih = (const float*)d_in[1];
    const float* W_hh = (const float*)d_in[2];
    const float* b_ih = (const float*)d_in[3];
    const float* b_hh = (const float*)d_in[4];
    const float* fc_W = (const float*)d_in[5];
    const float* fc_b = (const float*)d_in[6];
    (void)in_sizes; (void)n_in; (void)out_size;

    const int grid = 294;  // NB=14 -> 2 blocks per SM on 147 SMs
    lstm_fused<<<grid, NTHREADS>>>(x, W_ih, W_hh, b_ih, b_hh, fc_W, fc_b,
                                   (float*)d_out);
}

// round 17
// speedup vs baseline: 1.0982x; 1.0196x over previous
#include <cuda_runtime.h>

// LSTM (H=64, in=1, T=1024, B=4096) + Linear(64->30), fp32.
// R12 champion (3079us) + exact 0.5-prescale: i/f/o gate rows of W_hh, their
// W_ih entries and biases are multiplied by 0.5 at load (power of two ->
// bitwise exact), so sigmoid(g) = 0.5*tanh(g_half)+0.5 needs no input FMUL.
// Everything else identical to R12: 147 blocks x 256 thr; khalf/j/bhalf
// decomposition; 4 gate rows x 32 k in registers (rotated chunk order);
// shfl.bfly(1) k-combine; scalar glue; HW MUFU.TANH activations;
// divergence-free update of 7 owned batches; ping-pong h/x; 1 barrier/step.

#define HID      64
#define SEQ_T    1024
#define NBATCH   4096
#define NFC      30
#define NB       28
#define NTHREADS 256
#define XCHUNK   32
#define BPT      14       // batches touched per thread in matvec
#define BOWN     7        // batches owned per thread for c/h update

__device__ __forceinline__ float tanh_hw(float x) {
    float r; asm("tanh.approx.f32 %0, %1;" : "=f"(r) : "f"(x)); return r;
}
// input already halved via prescaled weights/bias
__device__ __forceinline__ float sigm_h(float xh) {
    return fmaf(0.5f, tanh_hw(xh), 0.5f);
}

__device__ __forceinline__ unsigned long long pack2(float lo, float hi) {
    unsigned long long r;
    asm("mov.b64 %0, {%1, %2};" : "=l"(r) : "f"(lo), "f"(hi));
    return r;
}
__device__ __forceinline__ void unpack2(unsigned long long v, float& lo, float& hi) {
    asm("mov.b64 {%0, %1}, %2;" : "=f"(lo), "=f"(hi) : "l"(v));
}
__device__ __forceinline__ void ffma2(unsigned long long& d,
                                      unsigned long long a,
                                      unsigned long long b) {
    asm("fma.rn.f32x2 %0, %1, %2, %0;" : "+l"(d) : "l"(a), "l"(b));
}

__global__ void __launch_bounds__(NTHREADS, 1)
lstm_fused(const float* __restrict__ x,      // [B, T]
           const float* __restrict__ W_ih,   // [256]
           const float* __restrict__ W_hh,   // [256, 64]
           const float* __restrict__ b_ih,   // [256]
           const float* __restrict__ b_hh,   // [256]
           const float* __restrict__ fc_W,   // [30, 64]
           const float* __restrict__ fc_b,   // [30]
           float* __restrict__ out)          // [B, 30]
{
    __shared__ __align__(16) float h_sm[2][NB][HID];     // ping-pong hidden
    __shared__ __align__(16) float x_sm[2][NB][XCHUNK];  // ping-pong x chunks
    __shared__ __align__(16) float fcW_sm[NFC][HID];
    __shared__ float fcb_sm[NFC];

    const int tid   = threadIdx.x;
    const int khalf = tid & 1;          // k half: 0 -> k[0..31], 1 -> k[32..63]
    const int j     = (tid >> 1) & 63;  // hidden unit
    const int bhalf = tid >> 7;         // batch half (0/1)
    const int b0    = blockIdx.x * NB;

    // --- weights: 4 gate rows, my 32 k-values, rotated chunk order so the
    //     two khalves hit disjoint smem bank quads. i/f/o rows scaled 0.5 ---
    const int rI = j, rF = HID + j, rG = 2 * HID + j, rO = 3 * HID + j;
    unsigned long long wI[16], wF[16], wG[16], wO[16];
    int hoff[8];  // byte offsets into an h row for chunk i
#pragma unroll
    for (int i = 0; i < 8; ++i) {
        int kb = khalf * 32 + (((i + khalf) & 7) << 2);
        hoff[i] = kb * 4;
        wI[2*i]   = pack2(0.5f*W_hh[rI*HID + kb],     0.5f*W_hh[rI*HID + kb + 1]);
        wI[2*i+1] = pack2(0.5f*W_hh[rI*HID + kb + 2], 0.5f*W_hh[rI*HID + kb + 3]);
        wF[2*i]   = pack2(0.5f*W_hh[rF*HID + kb],     0.5f*W_hh[rF*HID + kb + 1]);
        wF[2*i+1] = pack2(0.5f*W_hh[rF*HID + kb + 2], 0.5f*W_hh[rF*HID + kb + 3]);
        wG[2*i]   = pack2(W_hh[rG*HID + kb],          W_hh[rG*HID + kb + 1]);
        wG[2*i+1] = pack2(W_hh[rG*HID + kb + 2],      W_hh[rG*HID + kb + 3]);
        wO[2*i]   = pack2(0.5f*W_hh[rO*HID + kb],     0.5f*W_hh[rO*HID + kb + 1]);
        wO[2*i+1] = pack2(0.5f*W_hh[rO*HID + kb + 2], 0.5f*W_hh[rO*HID + kb + 3]);
    }
    const float wihI = 0.5f * W_ih[rI], wihF = 0.5f * W_ih[rF];
    const float wihG = W_ih[rG],        wihO = 0.5f * W_ih[rO];
    const float bI = 0.5f * (b_ih[rI] + b_hh[rI]);
    const float bF = 0.5f * (b_ih[rF] + b_hh[rF]);
    const float bG = b_ih[rG] + b_hh[rG];
    const float bO = 0.5f * (b_ih[rO] + b_hh[rO]);

    // --- FC weights to smem; h buf0 zero; x buf0 prologue (t=0..31) ---
    for (int i = tid; i < NFC * HID; i += NTHREADS)
        (&fcW_sm[0][0])[i] = fc_W[i];
    for (int i = tid; i < NFC; i += NTHREADS)
        fcb_sm[i] = fc_b[i];
    for (int i = tid; i < NB * HID; i += NTHREADS)
        (&h_sm[0][0][0])[i] = 0.0f;
    for (int i = tid; i < NB * XCHUNK; i += NTHREADS) {
        int b  = i / XCHUNK;
        int tt = i % XCHUNK;
        int gb = b0 + b; if (gb >= NBATCH) gb = NBATCH - 1;
        (&x_sm[0][0][0])[i] = x[gb * SEQ_T + tt];
    }

    float c_reg[BOWN];
#pragma unroll
    for (int s = 0; s < BOWN; ++s) c_reg[s] = 0.0f;

    for (int t = 0; t < SEQ_T; ++t) {
        const int rb = t & 1;           // h read buffer
        const int wb = rb ^ 1;          // h write buffer
        const int xb = (t >> 5) & 1;    // x read buffer

        // prefetch NEXT x chunk into the other buffer
        if ((t & (XCHUNK - 1)) == 0 && t + XCHUNK < SEQ_T) {
            for (int i = tid; i < NB * XCHUNK; i += NTHREADS) {
                int b  = i / XCHUNK;
                int tt = i % XCHUNK;
                int gb = b0 + b; if (gb >= NBATCH) gb = NBATCH - 1;
                x_sm[xb ^ 1][b][tt] = x[gb * SEQ_T + t + XCHUNK + tt];
            }
        }
        __syncthreads();  // h[rb] from prev step + x visible

        const int tx = t & (XCHUNK - 1);
        float gq[BOWN][4];  // full gates for the 7 batches this thread owns

#pragma unroll
        for (int s = 0; s < BPT; ++s) {
            const int b = bhalf * BPT + s;
            const char* hbase = (const char*)&h_sm[rb][b][0];

            unsigned long long aI = 0ull, aF = 0ull, aG = 0ull, aO = 0ull;
#pragma unroll
            for (int i = 0; i < 8; ++i) {
                ulonglong2 hv = *(const ulonglong2*)(hbase + hoff[i]);
                ffma2(aI, wI[2*i], hv.x); ffma2(aI, wI[2*i+1], hv.y);
                ffma2(aF, wF[2*i], hv.x); ffma2(aF, wF[2*i+1], hv.y);
                ffma2(aG, wG[2*i], hv.x); ffma2(aG, wG[2*i+1], hv.y);
                ffma2(aO, wO[2*i], hv.x); ffma2(aO, wO[2*i+1], hv.y);
            }
            float lo, hi, pI, pF, pG, pO;
            unpack2(aI, lo, hi); pI = lo + hi;
            unpack2(aF, lo, hi); pF = lo + hi;
            unpack2(aG, lo, hi); pG = lo + hi;
            unpack2(aO, lo, hi); pO = lo + hi;

            // combine k-halves with the paired lane (lane ^ 1, same warp)
            unsigned long long p01 = pack2(pI, pF);
            unsigned long long p23 = pack2(pG, pO);
            unsigned long long o01 = __shfl_xor_sync(0xffffffffu, p01, 1);
            unsigned long long o23 = __shfl_xor_sync(0xffffffffu, p23, 1);
            float oI, oF, oG, oO;
            unpack2(o01, oI, oF);
            unpack2(o23, oG, oO);

            const float xv = x_sm[xb][b][tx];
            float gI = pI + oI + fmaf(xv, wihI, bI);
            float gF = pF + oF + fmaf(xv, wihF, bF);
            float gG = pG + oG + fmaf(xv, wihG, bG);
            float gO = pO + oO + fmaf(xv, wihO, bO);

            // keep only batches this lane owns: khalf0 -> s 0..6, khalf1 -> 7..13
            if (s < BOWN) {
                if (khalf == 0) { gq[s][0]=gI; gq[s][1]=gF; gq[s][2]=gG; gq[s][3]=gO; }
            } else {
                if (khalf == 1) { gq[s-BOWN][0]=gI; gq[s-BOWN][1]=gF; gq[s-BOWN][2]=gG; gq[s-BOWN][3]=gO; }
            }
        }

        // ---- divergence-free update: each lane updates its 7 owned batches ----
#pragma unroll
        for (int q = 0; q < BOWN; ++q) {
            const int b = bhalf * BPT + khalf * BOWN + q;
            float ci = fmaf(sigm_h(gq[q][1]), c_reg[q],
                            sigm_h(gq[q][0]) * tanh_hw(gq[q][2]));
            c_reg[q] = ci;
            h_sm[wb][b][j] = sigm_h(gq[q][3]) * tanh_hw(ci);
        }
    }

    __syncthreads();  // final h (buffer 0, SEQ_T even) ready

    // ---- FC: out[b, f] = h[b,:] . fc_W[f,:] + fc_b[f] ----
    for (int task = tid; task < NB * NFC; task += NTHREADS) {
        int b = task / NFC;
        int f = task % NFC;
        int gb = b0 + b;
        if (gb < NBATCH) {
            float s = fcb_sm[f];
#pragma unroll
            for (int k = 0; k < HID; ++k)
                s = fmaf(h_sm[0][b][k], fcW_sm[f][k], s);
            out[gb * NFC + f] = s;
        }
    }
}

extern "C" void kernel_launch(void* const* d_in, const int* in_sizes, int n_in,
                              void* d_out, int out_size) {
    const float* x    = (const float*)d_in[0];
    const float* W_ih = (const float*)d_in[1];
    const float* W_hh = (const float*)d_in[2];
    const float* b_ih = (const float*)d_in[3];
    const float* b_hh = (const float*)d_in[4];
    const float* fc_W = (const float*)d_in[5];
    const float* fc_b = (const float*)d_in[6];
    (void)in_sizes; (void)n_in; (void)out_size;

    const int grid = (NBATCH + NB - 1) / NB;  // 147 blocks, 1 per SM
    lstm_fused<<<grid, NTHREADS>>>(x, W_ih, W_hh, b_ih, b_hh, fc_W, fc_b,
                                   (float*)d_out);
}